// round 14
// baseline (speedup 1.0000x reference)
#include <cuda_runtime.h>
#include <cuda_fp16.h>
#include <cstdint>

#define N_NODES 100000
#define N_EDGES 3200000
#define D 256
#define DH (D / 2)          // 128 half2 per row
#define SCAN_B 1024
#define N_SCAN_BLOCKS ((N_NODES + SCAN_B - 1) / SCAN_B)   // 98

#define AGG_READY 0x40000000
#define AGG_MASK  0x3FFFFFFF

// ---------------- device scratch (static, allowed) ----------------
__device__ __half2 g_support_h[(size_t)N_NODES * DH];   // X @ W in fp16 (51.2 MB)
// g_cnt and the scan aggregate flags share one symbol -> ONE memsetAsync clears both
__device__ int   g_cnt_agg[N_NODES + N_SCAN_BLOCKS];
#define G_CNT (g_cnt_agg)
#define G_AGG (g_cnt_agg + N_NODES)
__device__ int   g_row_ptr[N_NODES + 1];
__device__ int   g_cursor[N_NODES];
__device__ int2  g_edge[N_EDGES];    // packed (col, val as half2(v,v) bits)

// ---------------- GEMM config (tf32 tensor cores) ----------------
#define BM 128
#define BN 128
#define BK 32
#define AS_STRIDE 36
#define BS_STRIDE 136

#define GEMM_BLOCKS 1564            // 2 x 782
#define SCATTER_BLOCKS 3128         // 2*GEMM_BLOCKS >= ceil(800000/256)=3125
#define FUSED_BLOCKS (GEMM_BLOCKS + SCATTER_BLOCKS)   // 4692, mapped 1:2 interleaved

__device__ __forceinline__ uint32_t f2tf32(float f) {
    uint32_t o;
    asm("cvt.rna.tf32.f32 %0, %1;" : "=r"(o) : "f"(f));
    return o;
}

// ---------------- 1) histogram (standalone, runs first) ----------------
__global__ void hist_kernel(const int4* __restrict__ edge_row4) {
    int i = blockIdx.x * blockDim.x + threadIdx.x;
    if (i < N_EDGES / 4) {
        int4 r = edge_row4[i];
        atomicAdd(&G_CNT[r.x], 1);
        atomicAdd(&G_CNT[r.y], 1);
        atomicAdd(&G_CNT[r.z], 1);
        atomicAdd(&G_CNT[r.w], 1);
    }
}

// ---------------- 2) single-kernel scan (decoupled aggregate lookback) ----------------
// 98 blocks <= 148 SMs -> guaranteed single wave, spin-wait is deadlock-free.
__global__ void scan_kernel() {
    __shared__ int s[SCAN_B];
    const int t = threadIdx.x;
    const int b = blockIdx.x;
    const int i = b * SCAN_B + t;

    int v = (i < N_NODES) ? G_CNT[i] : 0;
    s[t] = v;
    __syncthreads();
    for (int off = 1; off < SCAN_B; off <<= 1) {
        int x = (t >= off) ? s[t - off] : 0;
        __syncthreads();
        s[t] += x;
        __syncthreads();
    }
    int incl      = s[t];            // local inclusive prefix
    int aggregate = s[SCAN_B - 1];   // block total

    if (t == 0) atomicExch(&G_AGG[b], aggregate | AGG_READY);

    int pred = 0;
    if (t < b) {
        int a;
        do { a = *(volatile int*)&G_AGG[t]; } while (!(a & AGG_READY));
        pred = a & AGG_MASK;
    }
    __syncthreads();
    s[t] = pred;
    __syncthreads();
    #pragma unroll
    for (int off = SCAN_B / 2; off > 0; off >>= 1) {
        if (t < off) s[t] += s[t + off];
        __syncthreads();
    }
    int prefix = s[0];

    if (i < N_NODES) {
        int gincl = prefix + incl;
        g_row_ptr[i + 1] = gincl;
        g_cursor[i]      = gincl - v;
        if (i == 0) g_row_ptr[0] = 0;
    }
}

// ---------------- 3) fused GEMM + scatter (independent once scan is done) ----------------
__device__ __forceinline__ int pack_val_h2(float v) {
    __half2 h = __float2half2_rn(v);
    return *(int*)&h;
}

__global__ void __launch_bounds__(256, 2) gemm_scatter_kernel(
        const float*  __restrict__ A,
        const float*  __restrict__ B,
        const int4*   __restrict__ edge_row4,
        const int4*   __restrict__ edge_col4,
        const float4* __restrict__ edge_val4) {
    __shared__ uint32_t As[BM * AS_STRIDE];
    __shared__ uint32_t Bs[BK * BS_STRIDE];

    const int tid = threadIdx.x;
    const int g3 = blockIdx.x / 3;
    const int r3 = blockIdx.x % 3;

    if (r3 != 0) {
        // ---- scatter branch (converts val -> half2 once, here) ----
        int h = g3 * 2 + (r3 - 1);               // 0..3127
        int i = h * 256 + tid;
        if (i < N_EDGES / 4) {
            int4   r = edge_row4[i];
            int4   c = edge_col4[i];
            float4 v = edge_val4[i];
            int p0 = atomicAdd(&g_cursor[r.x], 1);
            g_edge[p0] = make_int2(c.x, pack_val_h2(v.x));
            int p1 = atomicAdd(&g_cursor[r.y], 1);
            g_edge[p1] = make_int2(c.y, pack_val_h2(v.y));
            int p2 = atomicAdd(&g_cursor[r.z], 1);
            g_edge[p2] = make_int2(c.z, pack_val_h2(v.z));
            int p3 = atomicAdd(&g_cursor[r.w], 1);
            g_edge[p3] = make_int2(c.w, pack_val_h2(v.w));
        }
        return;
    }

    // ---- GEMM branch: block id g3 in [0, 1564) ----
    const int warp = tid >> 5;
    const int lane = tid & 31;
    const int warp_m = (warp >> 1) * 32;
    const int warp_n = (warp & 1) * 64;
    const int group  = lane >> 2;
    const int tig    = lane & 3;

    const int blockRow = (g3 >> 1) * BM;
    const int blockCol = (g3 & 1) * BN;

    float acc[2][8][4];
    #pragma unroll
    for (int mi = 0; mi < 2; mi++)
        #pragma unroll
        for (int ni = 0; ni < 8; ni++)
            #pragma unroll
            for (int c = 0; c < 4; c++) acc[mi][ni][c] = 0.f;

    for (int k0 = 0; k0 < D; k0 += BK) {
        #pragma unroll
        for (int i = 0; i < 4; i++) {
            int idx  = tid + i * 256;
            int row  = idx >> 3;
            int colv = (idx & 7) << 2;
            float4 v = make_float4(0.f, 0.f, 0.f, 0.f);
            int gr = blockRow + row;
            if (gr < N_NODES) v = *(const float4*)&A[(size_t)gr * D + k0 + colv];
            uint32_t* dst = &As[row * AS_STRIDE + colv];
            dst[0] = f2tf32(v.x); dst[1] = f2tf32(v.y);
            dst[2] = f2tf32(v.z); dst[3] = f2tf32(v.w);
        }
        #pragma unroll
        for (int i = 0; i < 4; i++) {
            int idx  = tid + i * 256;
            int row  = idx >> 5;
            int colv = (idx & 31) << 2;
            float4 v = *(const float4*)&B[(size_t)(k0 + row) * D + blockCol + colv];
            uint32_t* dst = &Bs[row * BS_STRIDE + colv];
            dst[0] = f2tf32(v.x); dst[1] = f2tf32(v.y);
            dst[2] = f2tf32(v.z); dst[3] = f2tf32(v.w);
        }
        __syncthreads();

        #pragma unroll
        for (int ks = 0; ks < 4; ks++) {
            const int kb = ks * 8;
            uint32_t af[2][4];
            #pragma unroll
            for (int mi = 0; mi < 2; mi++) {
                int m = warp_m + mi * 16 + group;
                af[mi][0] = As[(m    ) * AS_STRIDE + kb + tig    ];
                af[mi][1] = As[(m + 8) * AS_STRIDE + kb + tig    ];
                af[mi][2] = As[(m    ) * AS_STRIDE + kb + tig + 4];
                af[mi][3] = As[(m + 8) * AS_STRIDE + kb + tig + 4];
            }
            uint32_t bf[8][2];
            #pragma unroll
            for (int ni = 0; ni < 8; ni++) {
                int n = warp_n + ni * 8 + group;
                bf[ni][0] = Bs[(kb + tig    ) * BS_STRIDE + n];
                bf[ni][1] = Bs[(kb + tig + 4) * BS_STRIDE + n];
            }
            #pragma unroll
            for (int mi = 0; mi < 2; mi++)
                #pragma unroll
                for (int ni = 0; ni < 8; ni++) {
                    asm volatile(
                        "mma.sync.aligned.m16n8k8.row.col.f32.tf32.tf32.f32 "
                        "{%0,%1,%2,%3}, {%4,%5,%6,%7}, {%8,%9}, {%0,%1,%2,%3};\n"
                        : "+f"(acc[mi][ni][0]), "+f"(acc[mi][ni][1]),
                          "+f"(acc[mi][ni][2]), "+f"(acc[mi][ni][3])
                        : "r"(af[mi][0]), "r"(af[mi][1]), "r"(af[mi][2]), "r"(af[mi][3]),
                          "r"(bf[ni][0]), "r"(bf[ni][1]));
                }
        }
        __syncthreads();
    }

    #pragma unroll
    for (int mi = 0; mi < 2; mi++) {
        int row0 = blockRow + warp_m + mi * 16 + group;
        #pragma unroll
        for (int ni = 0; ni < 8; ni++) {
            int col = blockCol + warp_n + ni * 8 + tig * 2;
            if (row0 < N_NODES)
                g_support_h[(size_t)row0 * DH + (col >> 1)] =
                    __floats2half2_rn(acc[mi][ni][0], acc[mi][ni][1]);
            if (row0 + 8 < N_NODES)
                g_support_h[(size_t)(row0 + 8) * DH + (col >> 1)] =
                    __floats2half2_rn(acc[mi][ni][2], acc[mi][ni][3]);
        }
    }
}

// ---------------- 4) SpMM: warp per row, fp16 HFMA2 inner accumulate ----------------
// fp16 accumulate over 4 edges, flush to fp32. Remainder edges use exact fp32 path.
__device__ __forceinline__ void flush_h(float* a, __half2* hacc) {
    #pragma unroll
    for (int i = 0; i < 4; i++) {
        float2 f = __half22float2(hacc[i]);
        a[2 * i]     += f.x;
        a[2 * i + 1] += f.y;
        hacc[i] = __half2half2(__ushort_as_half(0));
    }
}

__global__ void spmm_kernel(const float* __restrict__ bias,
                            float* __restrict__ out) {
    int gwarp = (blockIdx.x * blockDim.x + threadIdx.x) >> 5;
    int lane  = threadIdx.x & 31;
    if (gwarp >= N_NODES) return;

    int beg = g_row_ptr[gwarp];
    int end = g_row_ptr[gwarp + 1];

    float a[8];
    #pragma unroll
    for (int i = 0; i < 8; i++) a[i] = 0.f;

    __half2 hacc[4];
    #pragma unroll
    for (int i = 0; i < 4; i++) hacc[i] = __half2half2(__ushort_as_half(0));

    int e = beg;
    for (; e + 7 < end; e += 8) {
        int2 ed[8];
        #pragma unroll
        for (int j = 0; j < 8; j++) ed[j] = g_edge[e + j];
        uint4 q[8];
        #pragma unroll
        for (int j = 0; j < 8; j++)
            q[j] = ((const uint4*)&g_support_h[(size_t)ed[j].x * DH])[lane];

        #pragma unroll
        for (int j = 0; j < 4; j++) {
            __half2 v = *(__half2*)&ed[j].y;
            const __half2* s = (const __half2*)&q[j];
            #pragma unroll
            for (int i = 0; i < 4; i++) hacc[i] = __hfma2(v, s[i], hacc[i]);
        }
        flush_h(a, hacc);
        #pragma unroll
        for (int j = 4; j < 8; j++) {
            __half2 v = *(__half2*)&ed[j].y;
            const __half2* s = (const __half2*)&q[j];
            #pragma unroll
            for (int i = 0; i < 4; i++) hacc[i] = __hfma2(v, s[i], hacc[i]);
        }
        flush_h(a, hacc);
    }
    // remainder: exact fp32 path (cvt + FFMA), <=7 edges
    for (; e < end; e++) {
        int2 ed = g_edge[e];
        uint4 q = ((const uint4*)&g_support_h[(size_t)ed.x * DH])[lane];
        float v = __half22float2(*(__half2*)&ed.y).x;
        const __half2* h = (const __half2*)&q;
        #pragma unroll
        for (int i = 0; i < 4; i++) {
            float2 f = __half22float2(h[i]);
            a[2 * i]     += v * f.x;
            a[2 * i + 1] += v * f.y;
        }
    }

    const float4* bp = (const float4*)&bias[lane * 8];
    float4 b0 = bp[0], b1 = bp[1];
    a[0] += b0.x; a[1] += b0.y; a[2] += b0.z; a[3] += b0.w;
    a[4] += b1.x; a[5] += b1.y; a[6] += b1.z; a[7] += b1.w;

    float4* o = (float4*)&out[(size_t)gwarp * D + lane * 8];
    o[0] = make_float4(a[0], a[1], a[2], a[3]);
    o[1] = make_float4(a[4], a[5], a[6], a[7]);
}

// ---------------- launch ----------------
extern "C" void kernel_launch(void* const* d_in, const int* in_sizes, int n_in,
                              void* d_out, int out_size) {
    const float* input_feature = (const float*)d_in[0];   // [100000,256]
    const int*   edge_row      = (const int*)  d_in[1];   // [3.2M]
    const int*   edge_col      = (const int*)  d_in[2];   // [3.2M]
    const float* edge_val      = (const float*)d_in[3];   // [3.2M]
    const float* weight        = (const float*)d_in[4];   // [256,256]
    const float* bias          = (const float*)d_in[5];   // [256]
    float* out = (float*)d_out;

    // clear counters + scan aggregate flags (one symbol, one memset)
    void* cnt_ptr = nullptr;
    cudaGetSymbolAddress(&cnt_ptr, g_cnt_agg);
    cudaMemsetAsync(cnt_ptr, 0, (N_NODES + N_SCAN_BLOCKS) * sizeof(int));

    // histogram of edge_row
    hist_kernel<<<(N_EDGES / 4 + 255) / 256, 256>>>((const int4*)edge_row);

    // single-kernel scan -> row_ptr + cursor
    scan_kernel<<<N_SCAN_BLOCKS, SCAN_B>>>();

    // fused: tf32 GEMM (support = X @ W, fp16 out)  ||  CSR scatter
    gemm_scatter_kernel<<<FUSED_BLOCKS, 256>>>(input_feature, weight,
                                               (const int4*)edge_row,
                                               (const int4*)edge_col,
                                               (const float4*)edge_val);

    // SpMM + bias
    spmm_kernel<<<(N_NODES * 32 + 255) / 256, 256>>>(bias, out);
}

// round 15
// speedup vs baseline: 1.4631x; 1.4631x over previous
#include <cuda_runtime.h>
#include <cuda_fp16.h>
#include <cstdint>

#define N_NODES 100000
#define N_EDGES 3200000
#define D 256
#define DH (D / 2)          // 128 half2 per row
#define SCAN_B 1024
#define N_SCAN_BLOCKS ((N_NODES + SCAN_B - 1) / SCAN_B)   // 98

#define AGG_READY 0x40000000
#define AGG_MASK  0x3FFFFFFF

// ---------------- device scratch (static, allowed) ----------------
__device__ __half2 g_support_h[(size_t)N_NODES * DH];   // X @ W in fp16 (51.2 MB)
// g_cnt and the scan aggregate flags share one symbol -> ONE memsetAsync clears both
__device__ int   g_cnt_agg[N_NODES + N_SCAN_BLOCKS];
#define G_CNT (g_cnt_agg)
#define G_AGG (g_cnt_agg + N_NODES)
__device__ int   g_row_ptr[N_NODES + 1];
__device__ int   g_cursor[N_NODES];
__device__ int2  g_edge[N_EDGES];    // packed (col, val-as-int fp32 bits)

// ---------------- GEMM config (tf32 tensor cores) ----------------
#define BM 128
#define BN 128
#define BK 32
#define AS_STRIDE 36
#define BS_STRIDE 136

#define GEMM_BLOCKS 1564            // 2 x 782
#define HIST_BLOCKS 3128            // 2*GEMM_BLOCKS >= ceil(800000/256)=3125
#define FUSED_BLOCKS (GEMM_BLOCKS + HIST_BLOCKS)   // 4692, mapped 1:2 interleaved

__device__ __forceinline__ uint32_t f2tf32(float f) {
    uint32_t o;
    asm("cvt.rna.tf32.f32 %0, %1;" : "=r"(o) : "f"(f));
    return o;
}

// ---------------- 1) fused GEMM (tf32 tensor cores) + edge histogram ----------------
__global__ void __launch_bounds__(256, 2) gemm_hist_kernel(const float* __restrict__ A,
                                                           const float* __restrict__ B,
                                                           const int4*  __restrict__ edge_row4) {
    __shared__ uint32_t As[BM * AS_STRIDE];
    __shared__ uint32_t Bs[BK * BS_STRIDE];

    const int tid = threadIdx.x;
    const int g3 = blockIdx.x / 3;
    const int r3 = blockIdx.x % 3;

    if (r3 != 0) {
        // ---- histogram branch ----
        int h = g3 * 2 + (r3 - 1);               // 0..3127
        int i = h * 256 + tid;
        if (i < N_EDGES / 4) {
            int4 r = edge_row4[i];
            atomicAdd(&G_CNT[r.x], 1);
            atomicAdd(&G_CNT[r.y], 1);
            atomicAdd(&G_CNT[r.z], 1);
            atomicAdd(&G_CNT[r.w], 1);
        }
        return;
    }

    // ---- GEMM branch: block id g3 in [0, 1564) ----
    const int warp = tid >> 5;
    const int lane = tid & 31;
    const int warp_m = (warp >> 1) * 32;
    const int warp_n = (warp & 1) * 64;
    const int group  = lane >> 2;
    const int tig    = lane & 3;

    const int blockRow = (g3 >> 1) * BM;
    const int blockCol = (g3 & 1) * BN;

    float acc[2][8][4];
    #pragma unroll
    for (int mi = 0; mi < 2; mi++)
        #pragma unroll
        for (int ni = 0; ni < 8; ni++)
            #pragma unroll
            for (int c = 0; c < 4; c++) acc[mi][ni][c] = 0.f;

    for (int k0 = 0; k0 < D; k0 += BK) {
        #pragma unroll
        for (int i = 0; i < 4; i++) {
            int idx  = tid + i * 256;
            int row  = idx >> 3;
            int colv = (idx & 7) << 2;
            float4 v = make_float4(0.f, 0.f, 0.f, 0.f);
            int gr = blockRow + row;
            if (gr < N_NODES) v = *(const float4*)&A[(size_t)gr * D + k0 + colv];
            uint32_t* dst = &As[row * AS_STRIDE + colv];
            dst[0] = f2tf32(v.x); dst[1] = f2tf32(v.y);
            dst[2] = f2tf32(v.z); dst[3] = f2tf32(v.w);
        }
        #pragma unroll
        for (int i = 0; i < 4; i++) {
            int idx  = tid + i * 256;
            int row  = idx >> 5;
            int colv = (idx & 31) << 2;
            float4 v = *(const float4*)&B[(size_t)(k0 + row) * D + blockCol + colv];
            uint32_t* dst = &Bs[row * BS_STRIDE + colv];
            dst[0] = f2tf32(v.x); dst[1] = f2tf32(v.y);
            dst[2] = f2tf32(v.z); dst[3] = f2tf32(v.w);
        }
        __syncthreads();

        #pragma unroll
        for (int ks = 0; ks < 4; ks++) {
            const int kb = ks * 8;
            uint32_t af[2][4];
            #pragma unroll
            for (int mi = 0; mi < 2; mi++) {
                int m = warp_m + mi * 16 + group;
                af[mi][0] = As[(m    ) * AS_STRIDE + kb + tig    ];
                af[mi][1] = As[(m + 8) * AS_STRIDE + kb + tig    ];
                af[mi][2] = As[(m    ) * AS_STRIDE + kb + tig + 4];
                af[mi][3] = As[(m + 8) * AS_STRIDE + kb + tig + 4];
            }
            uint32_t bf[8][2];
            #pragma unroll
            for (int ni = 0; ni < 8; ni++) {
                int n = warp_n + ni * 8 + group;
                bf[ni][0] = Bs[(kb + tig    ) * BS_STRIDE + n];
                bf[ni][1] = Bs[(kb + tig + 4) * BS_STRIDE + n];
            }
            #pragma unroll
            for (int mi = 0; mi < 2; mi++)
                #pragma unroll
                for (int ni = 0; ni < 8; ni++) {
                    asm volatile(
                        "mma.sync.aligned.m16n8k8.row.col.f32.tf32.tf32.f32 "
                        "{%0,%1,%2,%3}, {%4,%5,%6,%7}, {%8,%9}, {%0,%1,%2,%3};\n"
                        : "+f"(acc[mi][ni][0]), "+f"(acc[mi][ni][1]),
                          "+f"(acc[mi][ni][2]), "+f"(acc[mi][ni][3])
                        : "r"(af[mi][0]), "r"(af[mi][1]), "r"(af[mi][2]), "r"(af[mi][3]),
                          "r"(bf[ni][0]), "r"(bf[ni][1]));
                }
        }
        __syncthreads();
    }

    #pragma unroll
    for (int mi = 0; mi < 2; mi++) {
        int row0 = blockRow + warp_m + mi * 16 + group;
        #pragma unroll
        for (int ni = 0; ni < 8; ni++) {
            int col = blockCol + warp_n + ni * 8 + tig * 2;
            if (row0 < N_NODES)
                g_support_h[(size_t)row0 * DH + (col >> 1)] =
                    __floats2half2_rn(acc[mi][ni][0], acc[mi][ni][1]);
            if (row0 + 8 < N_NODES)
                g_support_h[(size_t)(row0 + 8) * DH + (col >> 1)] =
                    __floats2half2_rn(acc[mi][ni][2], acc[mi][ni][3]);
        }
    }
}

// ---------------- 2) single-kernel scan (decoupled aggregate lookback) ----------------
// 98 blocks <= 148 SMs -> guaranteed single wave, spin-wait is deadlock-free.
__global__ void scan_kernel() {
    __shared__ int s[SCAN_B];
    const int t = threadIdx.x;
    const int b = blockIdx.x;
    const int i = b * SCAN_B + t;

    int v = (i < N_NODES) ? G_CNT[i] : 0;
    s[t] = v;
    __syncthreads();
    for (int off = 1; off < SCAN_B; off <<= 1) {
        int x = (t >= off) ? s[t - off] : 0;
        __syncthreads();
        s[t] += x;
        __syncthreads();
    }
    int incl      = s[t];            // local inclusive prefix
    int aggregate = s[SCAN_B - 1];   // block total

    if (t == 0) atomicExch(&G_AGG[b], aggregate | AGG_READY);

    int pred = 0;
    if (t < b) {
        int a;
        do { a = *(volatile int*)&G_AGG[t]; } while (!(a & AGG_READY));
        pred = a & AGG_MASK;
    }
    __syncthreads();
    s[t] = pred;
    __syncthreads();
    #pragma unroll
    for (int off = SCAN_B / 2; off > 0; off >>= 1) {
        if (t < off) s[t] += s[t + off];
        __syncthreads();
    }
    int prefix = s[0];

    if (i < N_NODES) {
        int gincl = prefix + incl;
        g_row_ptr[i + 1] = gincl;
        g_cursor[i]      = gincl - v;
        if (i == 0) g_row_ptr[0] = 0;
    }
}

// ---------------- 3) scatter ----------------
__global__ void scatter_kernel(const int4*   __restrict__ edge_row4,
                               const int4*   __restrict__ edge_col4,
                               const float4* __restrict__ edge_val4) {
    int i = blockIdx.x * blockDim.x + threadIdx.x;
    if (i >= N_EDGES / 4) return;
    int4   r = edge_row4[i];
    int4   c = edge_col4[i];
    float4 v = edge_val4[i];
    int p0 = atomicAdd(&g_cursor[r.x], 1);
    g_edge[p0] = make_int2(c.x, __float_as_int(v.x));
    int p1 = atomicAdd(&g_cursor[r.y], 1);
    g_edge[p1] = make_int2(c.y, __float_as_int(v.y));
    int p2 = atomicAdd(&g_cursor[r.z], 1);
    g_edge[p2] = make_int2(c.z, __float_as_int(v.z));
    int p3 = atomicAdd(&g_cursor[r.w], 1);
    g_edge[p3] = make_int2(c.w, __float_as_int(v.w));
}

// ---------------- 4) SpMM: warp per row, fp16 gather, fp32 accumulate ----------------
// (R12 hot loop — 8 independent fp32 accumulator chains; proven 120us. Only change:
//  edge records loaded 2-at-a-time via int4 after aligning e to even index.)
__device__ __forceinline__ void fma8(float* acc, uint4 q, float v) {
    const __half2* h = (const __half2*)&q;
    #pragma unroll
    for (int i = 0; i < 4; i++) {
        float2 f = __half22float2(h[i]);
        acc[2 * i]     += v * f.x;
        acc[2 * i + 1] += v * f.y;
    }
}

__global__ void spmm_kernel(const float* __restrict__ bias,
                            float* __restrict__ out) {
    int gwarp = (blockIdx.x * blockDim.x + threadIdx.x) >> 5;
    int lane  = threadIdx.x & 31;
    if (gwarp >= N_NODES) return;

    int beg = g_row_ptr[gwarp];
    int end = g_row_ptr[gwarp + 1];

    float acc[8];
    #pragma unroll
    for (int i = 0; i < 8; i++) acc[i] = 0.f;

    int e = beg;
    // align to even edge index so int4 (2-edge) loads are 16B-aligned
    if ((e & 1) && e < end) {
        int2 ed = g_edge[e];
        uint4 q = ((const uint4*)&g_support_h[(size_t)ed.x * DH])[lane];
        fma8(acc, q, __int_as_float(ed.y));
        e++;
    }

    for (; e + 7 < end; e += 8) {
        const int4* ep = (const int4*)&g_edge[e];   // 16B-aligned: e is even
        int4 p0 = ep[0], p1 = ep[1], p2 = ep[2], p3 = ep[3];
        uint4 q0 = ((const uint4*)&g_support_h[(size_t)p0.x * DH])[lane];
        uint4 q1 = ((const uint4*)&g_support_h[(size_t)p0.z * DH])[lane];
        uint4 q2 = ((const uint4*)&g_support_h[(size_t)p1.x * DH])[lane];
        uint4 q3 = ((const uint4*)&g_support_h[(size_t)p1.z * DH])[lane];
        uint4 q4 = ((const uint4*)&g_support_h[(size_t)p2.x * DH])[lane];
        uint4 q5 = ((const uint4*)&g_support_h[(size_t)p2.z * DH])[lane];
        uint4 q6 = ((const uint4*)&g_support_h[(size_t)p3.x * DH])[lane];
        uint4 q7 = ((const uint4*)&g_support_h[(size_t)p3.z * DH])[lane];
        fma8(acc, q0, __int_as_float(p0.y));
        fma8(acc, q1, __int_as_float(p0.w));
        fma8(acc, q2, __int_as_float(p1.y));
        fma8(acc, q3, __int_as_float(p1.w));
        fma8(acc, q4, __int_as_float(p2.y));
        fma8(acc, q5, __int_as_float(p2.w));
        fma8(acc, q6, __int_as_float(p3.y));
        fma8(acc, q7, __int_as_float(p3.w));
    }
    for (; e < end; e++) {
        int2 ed = g_edge[e];
        uint4 q = ((const uint4*)&g_support_h[(size_t)ed.x * DH])[lane];
        fma8(acc, q, __int_as_float(ed.y));
    }

    const float4* bp = (const float4*)&bias[lane * 8];
    float4 b0 = bp[0], b1 = bp[1];
    acc[0] += b0.x; acc[1] += b0.y; acc[2] += b0.z; acc[3] += b0.w;
    acc[4] += b1.x; acc[5] += b1.y; acc[6] += b1.z; acc[7] += b1.w;

    float4* o = (float4*)&out[(size_t)gwarp * D + lane * 8];
    o[0] = make_float4(acc[0], acc[1], acc[2], acc[3]);
    o[1] = make_float4(acc[4], acc[5], acc[6], acc[7]);
}

// ---------------- launch ----------------
extern "C" void kernel_launch(void* const* d_in, const int* in_sizes, int n_in,
                              void* d_out, int out_size) {
    const float* input_feature = (const float*)d_in[0];   // [100000,256]
    const int*   edge_row      = (const int*)  d_in[1];   // [3.2M]
    const int*   edge_col      = (const int*)  d_in[2];   // [3.2M]
    const float* edge_val      = (const float*)d_in[3];   // [3.2M]
    const float* weight        = (const float*)d_in[4];   // [256,256]
    const float* bias          = (const float*)d_in[5];   // [256]
    float* out = (float*)d_out;

    // clear counters + scan aggregate flags (one symbol, one memset)
    void* cnt_ptr = nullptr;
    cudaGetSymbolAddress(&cnt_ptr, g_cnt_agg);
    cudaMemsetAsync(cnt_ptr, 0, (N_NODES + N_SCAN_BLOCKS) * sizeof(int));

    // fused: tf32 GEMM (support = X @ W, fp16 out) + edge_row histogram
    gemm_hist_kernel<<<FUSED_BLOCKS, 256>>>(input_feature, weight, (const int4*)edge_row);

    // single-kernel scan -> row_ptr + cursor
    scan_kernel<<<N_SCAN_BLOCKS, SCAN_B>>>();

    // scatter edges into CSR
    scatter_kernel<<<(N_EDGES / 4 + 255) / 256, 256>>>((const int4*)edge_row,
                                                       (const int4*)edge_col,
                                                       (const float4*)edge_val);

    // SpMM + bias
    spmm_kernel<<<(N_NODES * 32 + 255) / 256, 256>>>(bias, out);
}